// round 9
// baseline (speedup 1.0000x reference)
#include <cuda_runtime.h>
#include <cuda_bf16.h>
#include <math.h>
#include <cstdint>

#define D_MODEL 1024
#define D_STATE 16
#define D_CONV  4
#define D_INNER 2048
#define BATCH   2
#define SEQ     1024
#define ROWS    (BATCH * SEQ)          // 2048
#define E2      (2 * D_INNER)          // 4096

// ---------------- scratch (device globals; no allocations) ----------------
__device__ float g_xz[ROWS * E2];          // in_proj output; later: GEMM2 split-K partials
__device__ float g_xconv[ROWS * D_INNER];  // conv+silu output
__device__ float g_B[ROWS * D_STATE];
__device__ float g_C[ROWS * D_STATE];
__device__ float g_dtraw[ROWS];

// bf16 hi/lo split operands for tensor-core GEMMs
__device__ __nv_bfloat16 g_xhi[ROWS * D_MODEL];
__device__ __nv_bfloat16 g_xlo[ROWS * D_MODEL];
__device__ __nv_bfloat16 g_wihi[E2 * D_MODEL];
__device__ __nv_bfloat16 g_wilo[E2 * D_MODEL];
__device__ __nv_bfloat16 g_yyhi[ROWS * D_INNER];
__device__ __nv_bfloat16 g_yylo[ROWS * D_INNER];
__device__ __nv_bfloat16 g_wohi[D_MODEL * D_INNER];
__device__ __nv_bfloat16 g_wolo[D_MODEL * D_INNER];

// ---------------- PTX helpers ---------------------------------------------
__device__ __forceinline__ uint32_t smem_u32(const void* p) {
    uint32_t a;
    asm("{ .reg .u64 t; cvta.to.shared.u64 t, %1; cvt.u32.u64 %0, t; }" : "=r"(a) : "l"(p));
    return a;
}
#define CP_ASYNC16(smem, gmem) \
    asm volatile("cp.async.cg.shared.global [%0], [%1], 16;" :: "r"(smem), "l"(gmem))
#define CP_COMMIT() asm volatile("cp.async.commit_group;" ::: "memory")
#define CP_WAIT1()  asm volatile("cp.async.wait_group 1;" ::: "memory")
#define CP_WAIT0()  asm volatile("cp.async.wait_group 0;" ::: "memory")
#define LDMATRIX_X4(r0, r1, r2, r3, addr) \
    asm volatile("ldmatrix.sync.aligned.m8n8.x4.shared.b16 {%0,%1,%2,%3}, [%4];" \
        : "=r"(r0), "=r"(r1), "=r"(r2), "=r"(r3) : "r"(addr))
#define MMA16816(d, a, b) \
    asm volatile("mma.sync.aligned.m16n8k16.row.col.f32.bf16.bf16.f32 " \
        "{%0,%1,%2,%3}, {%4,%5,%6,%7}, {%8,%9}, {%0,%1,%2,%3};" \
        : "+f"((d)[0]), "+f"((d)[1]), "+f"((d)[2]), "+f"((d)[3]) \
        : "r"((a)[0]), "r"((a)[1]), "r"((a)[2]), "r"((a)[3]), "r"((b)[0]), "r"((b)[1]))

// ---------------- fused split fp32 -> bf16 hi/lo (3 tensors, 1 launch) -----
#define N4_X   (ROWS * D_MODEL / 4)        // 524288
#define N4_WI  (E2 * D_MODEL / 4)          // 1048576
#define N4_WO  (D_MODEL * D_INNER / 4)     // 524288
#define N4_TOT (N4_X + N4_WI + N4_WO)

__global__ void split3_bf16_kernel(const float* __restrict__ x,
                                   const float* __restrict__ wi,
                                   const float* __restrict__ wo) {
    int i = blockIdx.x * blockDim.x + threadIdx.x;
    if (i >= N4_TOT) return;
    const float* in;
    __nv_bfloat16 *hi, *lo;
    int j = i;
    if (j < N4_X)            { in = x;  hi = g_xhi;  lo = g_xlo; }
    else if ((j -= N4_X) < N4_WI) { in = wi; hi = g_wihi; lo = g_wilo; }
    else { j -= N4_WI;         in = wo; hi = g_wohi; lo = g_wolo; }

    float4 v = ((const float4*)in)[j];
    __nv_bfloat16 h0 = __float2bfloat16(v.x);
    __nv_bfloat16 h1 = __float2bfloat16(v.y);
    __nv_bfloat16 h2 = __float2bfloat16(v.z);
    __nv_bfloat16 h3 = __float2bfloat16(v.w);
    __nv_bfloat16 l0 = __float2bfloat16(v.x - __bfloat162float(h0));
    __nv_bfloat16 l1 = __float2bfloat16(v.y - __bfloat162float(h1));
    __nv_bfloat16 l2 = __float2bfloat16(v.z - __bfloat162float(h2));
    __nv_bfloat16 l3 = __float2bfloat16(v.w - __bfloat162float(h3));
    ((__nv_bfloat162*)hi)[2 * j]     = __nv_bfloat162(h0, h1);
    ((__nv_bfloat162*)hi)[2 * j + 1] = __nv_bfloat162(h2, h3);
    ((__nv_bfloat162*)lo)[2 * j]     = __nv_bfloat162(l0, l1);
    ((__nv_bfloat162*)lo)[2 * j + 1] = __nv_bfloat162(l2, l3);
}

// ---------------- HMMA split-bf16 GEMM: C = A @ W^T -----------------------
// Block 128x128, BK=32, 256 threads (8 warps, warp tile 64x32).
// 64B rows, XOR swizzle, 3-stage cp.async.
// RACE-FREE single barrier: wait -> barrier -> issue(kb+2) -> compute.
#define ROW_BYTES   64
#define TILE_SM     (128 * ROW_BYTES)        // 8192
#define STAGE_SM    (4 * TILE_SM)            // 32768
#define GEMM_SMEM   (3 * STAGE_SM)           // 98304

__global__ __launch_bounds__(256, 2) void gemm_hmma_x3(
    const __nv_bfloat16* __restrict__ Ahi, const __nv_bfloat16* __restrict__ Alo,
    const __nv_bfloat16* __restrict__ Whi, const __nv_bfloat16* __restrict__ Wlo,
    float* __restrict__ C, int M, int N, int Kfull, int Ksub) {
    extern __shared__ char dynsmem[];
    const uint32_t sbase = smem_u32(dynsmem);

    const int tid  = threadIdx.x;
    const int warp = tid >> 5;
    const int lane = tid & 31;
    const int rowBase = blockIdx.y * 128;
    const int colBase = blockIdx.x * 128;
    const int kBase   = blockIdx.z * Ksub;
    float* Cz = C + (size_t)blockIdx.z * M * N;

    const int ltile = tid >> 6;
    const int l64   = tid & 63;
    const __nv_bfloat16* lbase =
        (ltile == 0) ? Ahi : (ltile == 1) ? Alo : (ltile == 2) ? Whi : Wlo;
    const int lrbase = (ltile < 2) ? rowBase : colBase;

    const int wrow = (warp & 1) * 64;
    const int wcol = (warp >> 1) * 32;

    float acc[4][4][4];
#pragma unroll
    for (int i = 0; i < 4; i++)
#pragma unroll
        for (int j = 0; j < 4; j++)
#pragma unroll
            for (int r = 0; r < 4; r++) acc[i][j][r] = 0.f;

    const int nk = Ksub >> 5;
    const int lm_row = lane & 15;
    const int lm_ch  = lane >> 4;

    auto issue_stage = [&](int kb) {
        const int k0 = kBase + (kb << 5);
        const uint32_t stg = sbase + (kb % 3) * STAGE_SM + ltile * TILE_SM;
#pragma unroll
        for (int j = 0; j < 8; j++) {
            int idx = l64 + 64 * j;
            int row = idx >> 2;
            int cb  = idx & 3;
            const char* g = (const char*)lbase + ((size_t)(lrbase + row) * Kfull + k0) * 2 + cb * 16;
            uint32_t sc = cb ^ ((row >> 1) & 3);
            CP_ASYNC16(stg + row * ROW_BYTES + sc * 16, g);
        }
    };

    issue_stage(0); CP_COMMIT();
    if (nk > 1) { issue_stage(1); CP_COMMIT(); }

    for (int kb = 0; kb < nk; kb++) {
        const uint32_t stage = sbase + (kb % 3) * STAGE_SM;
        if (kb + 1 < nk) { CP_WAIT1(); }
        else { CP_WAIT0(); }
        __syncthreads();
        // Safe: all readers of stage (kb-1)%3 == (kb+2)%3 finished before this barrier.
        if (kb + 2 < nk) { issue_stage(kb + 2); CP_COMMIT(); }

#pragma unroll
        for (int k16 = 0; k16 < 2; k16++) {
            const int chunk = k16 * 2 + lm_ch;
            uint32_t aHi[4][4], aLo[4][4], bHi[2][4], bLo[2][4];
#pragma unroll
            for (int mi = 0; mi < 4; mi++) {
                int row = wrow + mi * 16 + lm_row;
                uint32_t sc = (uint32_t)(chunk ^ ((row >> 1) & 3));
                uint32_t addr = stage + 0 * TILE_SM + row * ROW_BYTES + sc * 16;
                LDMATRIX_X4(aHi[mi][0], aHi[mi][1], aHi[mi][2], aHi[mi][3], addr);
                addr += TILE_SM;
                LDMATRIX_X4(aLo[mi][0], aLo[mi][1], aLo[mi][2], aLo[mi][3], addr);
            }
#pragma unroll
            for (int np = 0; np < 2; np++) {
                int row = wcol + np * 16 + lm_row;
                uint32_t sc = (uint32_t)(chunk ^ ((row >> 1) & 3));
                uint32_t addr = stage + 2 * TILE_SM + row * ROW_BYTES + sc * 16;
                LDMATRIX_X4(bHi[np][0], bHi[np][1], bHi[np][2], bHi[np][3], addr);
                addr += TILE_SM;
                LDMATRIX_X4(bLo[np][0], bLo[np][1], bLo[np][2], bLo[np][3], addr);
            }
#pragma unroll
            for (int mi = 0; mi < 4; mi++) {
#pragma unroll
                for (int ni = 0; ni < 4; ni++) {
                    const int np = ni >> 1, sub = ni & 1;
                    uint32_t bh[2] = { bHi[np][sub], bHi[np][sub + 2] };
                    uint32_t bl[2] = { bLo[np][sub], bLo[np][sub + 2] };
                    MMA16816(acc[mi][ni], aHi[mi], bh);
                    MMA16816(acc[mi][ni], aLo[mi], bh);
                    MMA16816(acc[mi][ni], aHi[mi], bl);
                }
            }
        }
    }

#pragma unroll
    for (int mi = 0; mi < 4; mi++) {
#pragma unroll
        for (int ni = 0; ni < 4; ni++) {
            int r0 = rowBase + wrow + mi * 16 + (lane >> 2);
            int c0 = colBase + wcol + ni * 8 + (lane & 3) * 2;
            *(float2*)&Cz[(size_t)r0 * N + c0]       = make_float2(acc[mi][ni][0], acc[mi][ni][1]);
            *(float2*)&Cz[(size_t)(r0 + 8) * N + c0] = make_float2(acc[mi][ni][2], acc[mi][ni][3]);
        }
    }
}

// ---------------- split-K reduce: out = p0 + p1 ----------------------------
__global__ void addk_kernel(const float* __restrict__ p, float* __restrict__ out, int n4) {
    int i = blockIdx.x * blockDim.x + threadIdx.x;
    if (i >= n4) return;
    float4 a = ((const float4*)p)[i];
    float4 b = ((const float4*)p)[i + n4];
    ((float4*)out)[i] = make_float4(a.x + b.x, a.y + b.y, a.z + b.z, a.w + b.w);
}

// ---------------- depthwise causal conv(4) + bias + SiLU ------------------
__global__ void conv_silu_kernel(const float* __restrict__ conv_w,
                                 const float* __restrict__ conv_b) {
    int idx = blockIdx.x * blockDim.x + threadIdx.x;
    if (idx >= ROWS * D_INNER) return;
    int d = idx & (D_INNER - 1);
    int row = idx >> 11;
    int l = row & (SEQ - 1);
    int b = row >> 10;

    float acc = conv_b[d];
#pragma unroll
    for (int j = 0; j < D_CONV; j++) {
        int ls = l - (D_CONV - 1) + j;
        if (ls >= 0)
            acc = fmaf(conv_w[d * D_CONV + j],
                       g_xz[(size_t)(b * SEQ + ls) * E2 + d], acc);
    }
    g_xconv[idx] = acc / (1.f + __expf(-acc));
}

// ---------------- x_proj: 8 rows/block, 33 outputs each -------------------
__global__ __launch_bounds__(256) void xproj_kernel(const float* __restrict__ xpw) {
    extern __shared__ float xs[];                 // [8][2048] = 64KB
    const int row0 = blockIdx.x * 8;
    for (int i = threadIdx.x; i < 8 * D_INNER / 4; i += 256) {
        ((float4*)xs)[i] = ((const float4*)(g_xconv + (size_t)row0 * D_INNER))[i];
    }
    __syncthreads();

    const int warp = threadIdx.x >> 5, lane = threadIdx.x & 31;
    for (int n = warp; n < 2 * D_STATE + 1; n += 8) {
        const float* w = xpw + (size_t)n * D_INNER;
        float acc[8];
#pragma unroll
        for (int r = 0; r < 8; r++) acc[r] = 0.f;
        for (int k = lane * 4; k < D_INNER; k += 128) {
            float4 wv = *(const float4*)&w[k];
#pragma unroll
            for (int r = 0; r < 8; r++) {
                float4 xv = *(const float4*)&xs[r * D_INNER + k];
                acc[r] = fmaf(xv.x, wv.x, acc[r]);
                acc[r] = fmaf(xv.y, wv.y, acc[r]);
                acc[r] = fmaf(xv.z, wv.z, acc[r]);
                acc[r] = fmaf(xv.w, wv.w, acc[r]);
            }
        }
#pragma unroll
        for (int r = 0; r < 8; r++) {
            float s = acc[r];
#pragma unroll
            for (int off = 16; off; off >>= 1) s += __shfl_xor_sync(0xFFFFFFFFu, s, off);
            if (lane == 0) {
                int row = row0 + r;
                if (n < D_STATE)          g_B[row * D_STATE + n] = s;
                else if (n < 2 * D_STATE) g_C[row * D_STATE + n - D_STATE] = s;
                else                      g_dtraw[row] = s;
            }
        }
    }
}

// ---------------- selective scan: 4 lanes/channel, 32 channels/block ------
__global__ __launch_bounds__(128) void scan_kernel(const float* __restrict__ A_log,
                                                   const float* __restrict__ dtw,
                                                   const float* __restrict__ dtb) {
    const int lane = threadIdx.x & 31;
    const int warp = threadIdx.x >> 5;
    const int c = lane >> 2;
    const int j = lane & 3;
    const int ch = blockIdx.x * 32 + warp * 8 + c;   // 0..4095
    const int b = ch >> 11;
    const int d = ch & (D_INNER - 1);

    const float A0 = -expf(A_log[d * D_STATE + 4 * j + 0]);
    const float A1 = -expf(A_log[d * D_STATE + 4 * j + 1]);
    const float A2 = -expf(A_log[d * D_STATE + 4 * j + 2]);
    const float A3 = -expf(A_log[d * D_STATE + 4 * j + 3]);
    const float dtwd = dtw[d];
    const float dtbd = dtb[d];

    const size_t rbase = (size_t)b * SEQ;
    const float*  pu  = g_xconv + rbase * D_INNER + d;
    const float*  ptr = g_dtraw + rbase;
    const float4* pB  = (const float4*)(g_B + rbase * D_STATE) + j;
    const float4* pC  = (const float4*)(g_C + rbase * D_STATE) + j;
    const float*  pz  = g_xz + rbase * E2 + D_INNER + d;

    float u_pf[8], t_pf[8], z_pf[8];
    float4 B_pf[8], C_pf[8];
#pragma unroll
    for (int i = 0; i < 8; i++) {
        u_pf[i] = pu[(size_t)i * D_INNER];
        t_pf[i] = ptr[i];
        z_pf[i] = pz[(size_t)i * E2];
        B_pf[i] = pB[i * 4];
        C_pf[i] = pC[i * 4];
    }

    float s0 = 0.f, s1 = 0.f, s2 = 0.f, s3 = 0.f;
    const unsigned full = 0xFFFFFFFFu;

#pragma unroll 8
    for (int l = 0; l < SEQ; l++) {
        const int q = l & 7;
        const float u = u_pf[q], traw = t_pf[q], zv = z_pf[q];
        const float4 Bv = B_pf[q], Cv = C_pf[q];
        if (l + 8 < SEQ) {
            const int r = l + 8;
            u_pf[q] = pu[(size_t)r * D_INNER];
            t_pf[q] = ptr[r];
            z_pf[q] = pz[(size_t)r * E2];
            B_pf[q] = pB[r * 4];
            C_pf[q] = pC[r * 4];
        }
        float v = fmaf(traw, dtwd, dtbd);
        float dt = (v > 20.f) ? v : __logf(1.f + __expf(v));
        float dtu = dt * u;

        s0 = fmaf(__expf(dt * A0), s0, dtu * Bv.x);
        s1 = fmaf(__expf(dt * A1), s1, dtu * Bv.y);
        s2 = fmaf(__expf(dt * A2), s2, dtu * Bv.z);
        s3 = fmaf(__expf(dt * A3), s3, dtu * Bv.w);

        float p = s0 * Cv.x;
        p = fmaf(s1, Cv.y, p);
        p = fmaf(s2, Cv.z, p);
        p = fmaf(s3, Cv.w, p);
        p += __shfl_xor_sync(full, p, 1);
        p += __shfl_xor_sync(full, p, 2);

        if (j == 0) {
            float sz = zv / (1.f + __expf(-zv));
            float vv = p * sz;
            __nv_bfloat16 h = __float2bfloat16(vv);
            size_t o = (rbase + l) * D_INNER + d;
            g_yyhi[o] = h;
            g_yylo[o] = __float2bfloat16(vv - __bfloat162float(h));
        }
    }
}

// ---------------- launch --------------------------------------------------
extern "C" void kernel_launch(void* const* d_in, const int* in_sizes, int n_in,
                              void* d_out, int out_size) {
    const float* x         = (const float*)d_in[0];
    const float* in_proj_w = (const float*)d_in[1];
    const float* conv_w    = (const float*)d_in[2];
    const float* conv_b    = (const float*)d_in[3];
    const float* A_log     = (const float*)d_in[4];
    const float* x_proj_w  = (const float*)d_in[5];
    const float* dt_proj_w = (const float*)d_in[6];
    const float* dt_proj_b = (const float*)d_in[7];
    const float* out_proj_w= (const float*)d_in[8];
    float* out = (float*)d_out;

    float *xz_p;
    __nv_bfloat16 *xhi, *xlo, *wihi, *wilo, *yyhi, *yylo, *wohi, *wolo;
    cudaGetSymbolAddress((void**)&xz_p, g_xz);
    cudaGetSymbolAddress((void**)&xhi, g_xhi);
    cudaGetSymbolAddress((void**)&xlo, g_xlo);
    cudaGetSymbolAddress((void**)&wihi, g_wihi);
    cudaGetSymbolAddress((void**)&wilo, g_wilo);
    cudaGetSymbolAddress((void**)&yyhi, g_yyhi);
    cudaGetSymbolAddress((void**)&yylo, g_yylo);
    cudaGetSymbolAddress((void**)&wohi, g_wohi);
    cudaGetSymbolAddress((void**)&wolo, g_wolo);

    cudaFuncSetAttribute(gemm_hmma_x3, cudaFuncAttributeMaxDynamicSharedMemorySize, GEMM_SMEM);
    cudaFuncSetAttribute(xproj_kernel, cudaFuncAttributeMaxDynamicSharedMemorySize, 65536);

    // 0) split all operands to bf16 hi/lo (single launch)
    split3_bf16_kernel<<<(N4_TOT + 255) / 256, 256>>>(x, in_proj_w, out_proj_w);
    // 1) xz = x @ in_proj_w^T   (2048 x 4096, K=1024)
    {
        dim3 grid(E2 / 128, ROWS / 128, 1);
        gemm_hmma_x3<<<grid, 256, GEMM_SMEM>>>(xhi, xlo, wihi, wilo, xz_p,
                                               ROWS, E2, D_MODEL, D_MODEL);
    }
    // 2) conv + bias + silu
    {
        int n = ROWS * D_INNER;
        conv_silu_kernel<<<(n + 255) / 256, 256>>>(conv_w, conv_b);
    }
    // 3) x_proj (B, C, dtraw)  — 8 rows per block
    xproj_kernel<<<ROWS / 8, 256, 65536>>>(x_proj_w);
    // 4) selective scan (+ fused dt, silu(z) epilogue; writes bf16 hi/lo)
    scan_kernel<<<(BATCH * D_INNER) / 32, 128>>>(A_log, dt_proj_w, dt_proj_b);
    // 5) out = yy @ out_proj_w^T   (2048 x 1024, K=2048) — split-K=2 into g_xz
    {
        dim3 grid(D_MODEL / 128, ROWS / 128, 2);
        gemm_hmma_x3<<<grid, 256, GEMM_SMEM>>>(yyhi, yylo, wohi, wolo, xz_p,
                                               ROWS, D_MODEL, D_INNER, D_INNER / 2);
        int n4 = ROWS * D_MODEL / 4;
        addk_kernel<<<(n4 + 255) / 256, 256>>>(xz_p, out, n4);
    }
}

// round 10
// speedup vs baseline: 1.5824x; 1.5824x over previous
#include <cuda_runtime.h>
#include <cuda_bf16.h>
#include <math.h>
#include <cstdint>

#define D_MODEL 1024
#define D_STATE 16
#define D_CONV  4
#define D_INNER 2048
#define BATCH   2
#define SEQ     1024
#define ROWS    (BATCH * SEQ)          // 2048
#define E2      (2 * D_INNER)          // 4096

// ---------------- scratch (device globals; no allocations) ----------------
__device__ float g_xz[ROWS * E2];          // in_proj output; later: GEMM2 split-K partials
__device__ float g_xconv[ROWS * D_INNER];  // conv+silu output
__device__ float g_B[ROWS * D_STATE];
__device__ float g_C[ROWS * D_STATE];
__device__ float g_dtraw[ROWS];

// bf16 hi/lo split operands for tensor-core GEMMs
__device__ __nv_bfloat16 g_xhi[ROWS * D_MODEL];
__device__ __nv_bfloat16 g_xlo[ROWS * D_MODEL];
__device__ __nv_bfloat16 g_wihi[E2 * D_MODEL];
__device__ __nv_bfloat16 g_wilo[E2 * D_MODEL];
__device__ __nv_bfloat16 g_yyhi[ROWS * D_INNER];
__device__ __nv_bfloat16 g_yylo[ROWS * D_INNER];
__device__ __nv_bfloat16 g_wohi[D_MODEL * D_INNER];
__device__ __nv_bfloat16 g_wolo[D_MODEL * D_INNER];

// ---------------- PTX helpers ---------------------------------------------
__device__ __forceinline__ uint32_t smem_u32(const void* p) {
    uint32_t a;
    asm("{ .reg .u64 t; cvta.to.shared.u64 t, %1; cvt.u32.u64 %0, t; }" : "=r"(a) : "l"(p));
    return a;
}
#define CP_ASYNC16(smem, gmem) \
    asm volatile("cp.async.cg.shared.global [%0], [%1], 16;" :: "r"(smem), "l"(gmem))
#define CP_COMMIT() asm volatile("cp.async.commit_group;" ::: "memory")
#define CP_WAIT2()  asm volatile("cp.async.wait_group 2;" ::: "memory")
#define CP_WAIT1()  asm volatile("cp.async.wait_group 1;" ::: "memory")
#define CP_WAIT0()  asm volatile("cp.async.wait_group 0;" ::: "memory")
#define LDMATRIX_X4(r0, r1, r2, r3, addr) \
    asm volatile("ldmatrix.sync.aligned.m8n8.x4.shared.b16 {%0,%1,%2,%3}, [%4];" \
        : "=r"(r0), "=r"(r1), "=r"(r2), "=r"(r3) : "r"(addr))
#define MMA16816(d, a, b) \
    asm volatile("mma.sync.aligned.m16n8k16.row.col.f32.bf16.bf16.f32 " \
        "{%0,%1,%2,%3}, {%4,%5,%6,%7}, {%8,%9}, {%0,%1,%2,%3};" \
        : "+f"((d)[0]), "+f"((d)[1]), "+f"((d)[2]), "+f"((d)[3]) \
        : "r"((a)[0]), "r"((a)[1]), "r"((a)[2]), "r"((a)[3]), "r"((b)[0]), "r"((b)[1]))

// ---------------- split fp32 -> bf16 hi/lo ---------------------------------
__global__ void split_bf16_kernel(const float* __restrict__ in,
                                  __nv_bfloat16* __restrict__ hi,
                                  __nv_bfloat16* __restrict__ lo, int n4) {
    int i = blockIdx.x * blockDim.x + threadIdx.x;
    if (i >= n4) return;
    float4 v = ((const float4*)in)[i];
    __nv_bfloat16 h0 = __float2bfloat16(v.x);
    __nv_bfloat16 h1 = __float2bfloat16(v.y);
    __nv_bfloat16 h2 = __float2bfloat16(v.z);
    __nv_bfloat16 h3 = __float2bfloat16(v.w);
    __nv_bfloat16 l0 = __float2bfloat16(v.x - __bfloat162float(h0));
    __nv_bfloat16 l1 = __float2bfloat16(v.y - __bfloat162float(h1));
    __nv_bfloat16 l2 = __float2bfloat16(v.z - __bfloat162float(h2));
    __nv_bfloat16 l3 = __float2bfloat16(v.w - __bfloat162float(h3));
    ((__nv_bfloat162*)hi)[2 * i]     = __nv_bfloat162(h0, h1);
    ((__nv_bfloat162*)hi)[2 * i + 1] = __nv_bfloat162(h2, h3);
    ((__nv_bfloat162*)lo)[2 * i]     = __nv_bfloat162(l0, l1);
    ((__nv_bfloat162*)lo)[2 * i + 1] = __nv_bfloat162(l2, l3);
}

// ---------------- HMMA split-bf16 GEMM: C = A @ W^T -----------------------
// Block 128x128, BK=32, 256 threads (8 warps, warp tile 64x32).
// 64B rows, XOR swizzle, 3-stage cp.async, TWO barriers per k-block
// (trailing barrier makes issue(kb+2)->stage (kb-1)%3 provably race-free).
// split-K via blockIdx.z (partial written to C + z*M*N).
#define ROW_BYTES   64
#define TILE_SM     (128 * ROW_BYTES)        // 8192
#define STAGE_SM    (4 * TILE_SM)            // 32768
#define GEMM_SMEM   (3 * STAGE_SM)           // 98304

__global__ __launch_bounds__(256, 2) void gemm_hmma_x3(
    const __nv_bfloat16* __restrict__ Ahi, const __nv_bfloat16* __restrict__ Alo,
    const __nv_bfloat16* __restrict__ Whi, const __nv_bfloat16* __restrict__ Wlo,
    float* __restrict__ C, int M, int N, int Kfull, int Ksub) {
    extern __shared__ char dynsmem[];
    const uint32_t sbase = smem_u32(dynsmem);

    const int tid  = threadIdx.x;
    const int warp = tid >> 5;
    const int lane = tid & 31;
    const int rowBase = blockIdx.y * 128;
    const int colBase = blockIdx.x * 128;
    const int kBase   = blockIdx.z * Ksub;
    float* Cz = C + (size_t)blockIdx.z * M * N;

    const int ltile = tid >> 6;
    const int l64   = tid & 63;
    const __nv_bfloat16* lbase =
        (ltile == 0) ? Ahi : (ltile == 1) ? Alo : (ltile == 2) ? Whi : Wlo;
    const int lrbase = (ltile < 2) ? rowBase : colBase;

    const int wrow = (warp & 1) * 64;
    const int wcol = (warp >> 1) * 32;

    float acc[4][4][4];
#pragma unroll
    for (int i = 0; i < 4; i++)
#pragma unroll
        for (int j = 0; j < 4; j++)
#pragma unroll
            for (int r = 0; r < 4; r++) acc[i][j][r] = 0.f;

    const int nk = Ksub >> 5;
    const int lm_row = lane & 15;
    const int lm_ch  = lane >> 4;

    auto issue_stage = [&](int kb) {
        const int k0 = kBase + (kb << 5);
        const uint32_t stg = sbase + (kb % 3) * STAGE_SM + ltile * TILE_SM;
#pragma unroll
        for (int j = 0; j < 8; j++) {
            int idx = l64 + 64 * j;
            int row = idx >> 2;
            int cb  = idx & 3;
            const char* g = (const char*)lbase + ((size_t)(lrbase + row) * Kfull + k0) * 2 + cb * 16;
            uint32_t sc = cb ^ ((row >> 1) & 3);
            CP_ASYNC16(stg + row * ROW_BYTES + sc * 16, g);
        }
    };

    issue_stage(0); CP_COMMIT();
    if (nk > 1) { issue_stage(1); CP_COMMIT(); }

    for (int kb = 0; kb < nk; kb++) {
        const uint32_t stage = sbase + (kb % 3) * STAGE_SM;
        if (kb + 2 < nk) { issue_stage(kb + 2); CP_COMMIT(); CP_WAIT2(); }
        else if (kb + 1 < nk) { CP_WAIT1(); }
        else { CP_WAIT0(); }
        __syncthreads();

#pragma unroll
        for (int k16 = 0; k16 < 2; k16++) {
            const int chunk = k16 * 2 + lm_ch;
            uint32_t aHi[4][4], aLo[4][4], bHi[2][4], bLo[2][4];
#pragma unroll
            for (int mi = 0; mi < 4; mi++) {
                int row = wrow + mi * 16 + lm_row;
                uint32_t sc = (uint32_t)(chunk ^ ((row >> 1) & 3));
                uint32_t addr = stage + 0 * TILE_SM + row * ROW_BYTES + sc * 16;
                LDMATRIX_X4(aHi[mi][0], aHi[mi][1], aHi[mi][2], aHi[mi][3], addr);
                addr += TILE_SM;
                LDMATRIX_X4(aLo[mi][0], aLo[mi][1], aLo[mi][2], aLo[mi][3], addr);
            }
#pragma unroll
            for (int np = 0; np < 2; np++) {
                int row = wcol + np * 16 + lm_row;
                uint32_t sc = (uint32_t)(chunk ^ ((row >> 1) & 3));
                uint32_t addr = stage + 2 * TILE_SM + row * ROW_BYTES + sc * 16;
                LDMATRIX_X4(bHi[np][0], bHi[np][1], bHi[np][2], bHi[np][3], addr);
                addr += TILE_SM;
                LDMATRIX_X4(bLo[np][0], bLo[np][1], bLo[np][2], bLo[np][3], addr);
            }
#pragma unroll
            for (int mi = 0; mi < 4; mi++) {
#pragma unroll
                for (int ni = 0; ni < 4; ni++) {
                    const int np = ni >> 1, sub = ni & 1;
                    uint32_t bh[2] = { bHi[np][sub], bHi[np][sub + 2] };
                    uint32_t bl[2] = { bLo[np][sub], bLo[np][sub + 2] };
                    MMA16816(acc[mi][ni], aHi[mi], bh);
                    MMA16816(acc[mi][ni], aLo[mi], bh);
                    MMA16816(acc[mi][ni], aHi[mi], bl);
                }
            }
        }
        __syncthreads();
    }

#pragma unroll
    for (int mi = 0; mi < 4; mi++) {
#pragma unroll
        for (int ni = 0; ni < 4; ni++) {
            int r0 = rowBase + wrow + mi * 16 + (lane >> 2);
            int c0 = colBase + wcol + ni * 8 + (lane & 3) * 2;
            *(float2*)&Cz[(size_t)r0 * N + c0]       = make_float2(acc[mi][ni][0], acc[mi][ni][1]);
            *(float2*)&Cz[(size_t)(r0 + 8) * N + c0] = make_float2(acc[mi][ni][2], acc[mi][ni][3]);
        }
    }
}

// ---------------- split-K reduce: out = p0 + p1 ----------------------------
__global__ void addk_kernel(const float* __restrict__ p, float* __restrict__ out, int n4) {
    int i = blockIdx.x * blockDim.x + threadIdx.x;
    if (i >= n4) return;
    float4 a = ((const float4*)p)[i];
    float4 b = ((const float4*)p)[i + n4];
    ((float4*)out)[i] = make_float4(a.x + b.x, a.y + b.y, a.z + b.z, a.w + b.w);
}

// ---------------- depthwise causal conv(4) + bias + SiLU ------------------
__global__ void conv_silu_kernel(const float* __restrict__ conv_w,
                                 const float* __restrict__ conv_b) {
    int idx = blockIdx.x * blockDim.x + threadIdx.x;
    if (idx >= ROWS * D_INNER) return;
    int d = idx & (D_INNER - 1);
    int row = idx >> 11;
    int l = row & (SEQ - 1);
    int b = row >> 10;

    float acc = conv_b[d];
#pragma unroll
    for (int j = 0; j < D_CONV; j++) {
        int ls = l - (D_CONV - 1) + j;
        if (ls >= 0)
            acc = fmaf(conv_w[d * D_CONV + j],
                       g_xz[(size_t)(b * SEQ + ls) * E2 + d], acc);
    }
    g_xconv[idx] = acc / (1.f + __expf(-acc));
}

// ---------------- x_proj: 4 rows/block, 33 outputs each -------------------
__global__ __launch_bounds__(256) void xproj_kernel(const float* __restrict__ xpw) {
    extern __shared__ float xs[];                 // [4][2048] = 32KB
    const int row0 = blockIdx.x * 4;
    for (int i = threadIdx.x; i < 4 * D_INNER / 4; i += 256) {
        ((float4*)xs)[i] = ((const float4*)(g_xconv + (size_t)row0 * D_INNER))[i];
    }
    __syncthreads();

    const int warp = threadIdx.x >> 5, lane = threadIdx.x & 31;
    for (int n = warp; n < 2 * D_STATE + 1; n += 8) {
        const float* w = xpw + (size_t)n * D_INNER;
        float acc[4];
#pragma unroll
        for (int r = 0; r < 4; r++) acc[r] = 0.f;
        for (int k = lane * 4; k < D_INNER; k += 128) {
            float4 wv = *(const float4*)&w[k];
#pragma unroll
            for (int r = 0; r < 4; r++) {
                float4 xv = *(const float4*)&xs[r * D_INNER + k];
                acc[r] = fmaf(xv.x, wv.x, acc[r]);
                acc[r] = fmaf(xv.y, wv.y, acc[r]);
                acc[r] = fmaf(xv.z, wv.z, acc[r]);
                acc[r] = fmaf(xv.w, wv.w, acc[r]);
            }
        }
#pragma unroll
        for (int r = 0; r < 4; r++) {
            float s = acc[r];
#pragma unroll
            for (int off = 16; off; off >>= 1) s += __shfl_xor_sync(0xFFFFFFFFu, s, off);
            if (lane == 0) {
                int row = row0 + r;
                if (n < D_STATE)          g_B[row * D_STATE + n] = s;
                else if (n < 2 * D_STATE) g_C[row * D_STATE + n - D_STATE] = s;
                else                      g_dtraw[row] = s;
            }
        }
    }
}

// ---------------- selective scan: 4 lanes/channel, 8 channels/warp --------
__global__ __launch_bounds__(32) void scan_kernel(const float* __restrict__ A_log,
                                                  const float* __restrict__ dtw,
                                                  const float* __restrict__ dtb) {
    const int lane = threadIdx.x;
    const int c = lane >> 2;
    const int j = lane & 3;
    const int ch = blockIdx.x * 8 + c;          // 0..4095
    const int b = ch >> 11;
    const int d = ch & (D_INNER - 1);

    const float A0 = -expf(A_log[d * D_STATE + 4 * j + 0]);
    const float A1 = -expf(A_log[d * D_STATE + 4 * j + 1]);
    const float A2 = -expf(A_log[d * D_STATE + 4 * j + 2]);
    const float A3 = -expf(A_log[d * D_STATE + 4 * j + 3]);
    const float dtwd = dtw[d];
    const float dtbd = dtb[d];

    const size_t rbase = (size_t)b * SEQ;
    const float*  pu  = g_xconv + rbase * D_INNER + d;
    const float*  ptr = g_dtraw + rbase;
    const float4* pB  = (const float4*)(g_B + rbase * D_STATE) + j;
    const float4* pC  = (const float4*)(g_C + rbase * D_STATE) + j;
    const float*  pz  = g_xz + rbase * E2 + D_INNER + d;

    float u_pf[8], t_pf[8], z_pf[8];
    float4 B_pf[8], C_pf[8];
#pragma unroll
    for (int i = 0; i < 8; i++) {
        u_pf[i] = pu[(size_t)i * D_INNER];
        t_pf[i] = ptr[i];
        z_pf[i] = pz[(size_t)i * E2];
        B_pf[i] = pB[i * 4];
        C_pf[i] = pC[i * 4];
    }

    float s0 = 0.f, s1 = 0.f, s2 = 0.f, s3 = 0.f;
    const unsigned full = 0xFFFFFFFFu;

#pragma unroll 8
    for (int l = 0; l < SEQ; l++) {
        const int q = l & 7;
        const float u = u_pf[q], traw = t_pf[q], zv = z_pf[q];
        const float4 Bv = B_pf[q], Cv = C_pf[q];
        if (l + 8 < SEQ) {
            const int r = l + 8;
            u_pf[q] = pu[(size_t)r * D_INNER];
            t_pf[q] = ptr[r];
            z_pf[q] = pz[(size_t)r * E2];
            B_pf[q] = pB[r * 4];
            C_pf[q] = pC[r * 4];
        }
        float v = fmaf(traw, dtwd, dtbd);
        float dt = (v > 20.f) ? v : __logf(1.f + __expf(v));
        float dtu = dt * u;

        s0 = fmaf(__expf(dt * A0), s0, dtu * Bv.x);
        s1 = fmaf(__expf(dt * A1), s1, dtu * Bv.y);
        s2 = fmaf(__expf(dt * A2), s2, dtu * Bv.z);
        s3 = fmaf(__expf(dt * A3), s3, dtu * Bv.w);

        float p = s0 * Cv.x;
        p = fmaf(s1, Cv.y, p);
        p = fmaf(s2, Cv.z, p);
        p = fmaf(s3, Cv.w, p);
        p += __shfl_xor_sync(full, p, 1);
        p += __shfl_xor_sync(full, p, 2);

        if (j == 0) {
            float sz = zv / (1.f + __expf(-zv));
            float vv = p * sz;
            __nv_bfloat16 h = __float2bfloat16(vv);
            size_t o = (rbase + l) * D_INNER + d;
            g_yyhi[o] = h;
            g_yylo[o] = __float2bfloat16(vv - __bfloat162float(h));
        }
    }
}

// ---------------- launch --------------------------------------------------
extern "C" void kernel_launch(void* const* d_in, const int* in_sizes, int n_in,
                              void* d_out, int out_size) {
    const float* x         = (const float*)d_in[0];
    const float* in_proj_w = (const float*)d_in[1];
    const float* conv_w    = (const float*)d_in[2];
    const float* conv_b    = (const float*)d_in[3];
    const float* A_log     = (const float*)d_in[4];
    const float* x_proj_w  = (const float*)d_in[5];
    const float* dt_proj_w = (const float*)d_in[6];
    const float* dt_proj_b = (const float*)d_in[7];
    const float* out_proj_w= (const float*)d_in[8];
    float* out = (float*)d_out;

    float *xz_p;
    __nv_bfloat16 *xhi, *xlo, *wihi, *wilo, *yyhi, *yylo, *wohi, *wolo;
    cudaGetSymbolAddress((void**)&xz_p, g_xz);
    cudaGetSymbolAddress((void**)&xhi, g_xhi);
    cudaGetSymbolAddress((void**)&xlo, g_xlo);
    cudaGetSymbolAddress((void**)&wihi, g_wihi);
    cudaGetSymbolAddress((void**)&wilo, g_wilo);
    cudaGetSymbolAddress((void**)&yyhi, g_yyhi);
    cudaGetSymbolAddress((void**)&yylo, g_yylo);
    cudaGetSymbolAddress((void**)&wohi, g_wohi);
    cudaGetSymbolAddress((void**)&wolo, g_wolo);

    cudaFuncSetAttribute(gemm_hmma_x3, cudaFuncAttributeMaxDynamicSharedMemorySize, GEMM_SMEM);
    cudaFuncSetAttribute(xproj_kernel, cudaFuncAttributeMaxDynamicSharedMemorySize, 32768);

    // 0) split operands to bf16 hi/lo
    {
        int n4 = ROWS * D_MODEL / 4;
        split_bf16_kernel<<<(n4 + 255) / 256, 256>>>(x, xhi, xlo, n4);
        n4 = E2 * D_MODEL / 4;
        split_bf16_kernel<<<(n4 + 255) / 256, 256>>>(in_proj_w, wihi, wilo, n4);
        n4 = D_MODEL * D_INNER / 4;
        split_bf16_kernel<<<(n4 + 255) / 256, 256>>>(out_proj_w, wohi, wolo, n4);
    }
    // 1) xz = x @ in_proj_w^T   (2048 x 4096, K=1024)
    {
        dim3 grid(E2 / 128, ROWS / 128, 1);
        gemm_hmma_x3<<<grid, 256, GEMM_SMEM>>>(xhi, xlo, wihi, wilo, xz_p,
                                               ROWS, E2, D_MODEL, D_MODEL);
    }
    // 2) conv + bias + silu
    {
        int n = ROWS * D_INNER;
        conv_silu_kernel<<<(n + 255) / 256, 256>>>(conv_w, conv_b);
    }
    // 3) x_proj (B, C, dtraw)  — 4 rows per block
    xproj_kernel<<<ROWS / 4, 256, 32768>>>(x_proj_w);
    // 4) selective scan (+ fused dt, silu(z) epilogue; writes bf16 hi/lo)
    scan_kernel<<<(BATCH * D_INNER) / 8, 32>>>(A_log, dt_proj_w, dt_proj_b);
    // 5) out = yy @ out_proj_w^T   (2048 x 1024, K=2048) — split-K=2 into g_xz
    {
        dim3 grid(D_MODEL / 128, ROWS / 128, 2);
        gemm_hmma_x3<<<grid, 256, GEMM_SMEM>>>(yyhi, yylo, wohi, wolo, xz_p,
                                               ROWS, D_MODEL, D_INNER, D_INNER / 2);
        int n4 = ROWS * D_MODEL / 4;
        addk_kernel<<<(n4 + 255) / 256, 256>>>(xz_p, out, n4);
    }
}